// round 9
// baseline (speedup 1.0000x reference)
#include <cuda_runtime.h>

// CRF Viterbi decode: B=128, S=512, T=64.
// TWO batches per CTA, interleaved in the same 128 threads so batch B's
// instructions fill batch A's latency stalls (barrier/LDS/chain latencies
// were fully exposed and correlated across warps at 1 batch/CTA).
// Warp w owns tags 16w..16w+15; lanes 0-15 = preds [0,32), lanes 16-31 =
// preds [32,64). ONE __syncthreads per step; cross-segment combine via
// __shfl_xor(16). Bit-exact with reference: v = (f + trans[i][j]) + part[i];
// first-occurrence argmax (fmax value chains, pred-select indices,
// ascending strict-> combines, seg0 wins ties). Output float32.

#define SS 512
#define TT 64
#define START_TAG 62
#define STOP_TAG 63
#define NEG_INF (-3.402823466e+38f)
#define NTHR 128
#define NB 2
#define BP_BYTES (NB * SS * TT)

// 32-wide argmax reduction over this thread's predecessor segment.
// PARTROW: float[TT] partition; F: this tag's feat; outputs best val + index.
#define REDUCE32(PARTROW, F, OUTB, OUTA) do {                                 \
    float pv[32];                                                             \
    { const float4* p4 = (const float4*)(&(PARTROW)[i0]);                     \
      _Pragma("unroll")                                                       \
      for (int q = 0; q < 8; ++q) {                                           \
          float4 v4 = p4[q];                                                  \
          pv[4*q+0] = v4.x; pv[4*q+1] = v4.y;                                 \
          pv[4*q+2] = v4.z; pv[4*q+3] = v4.w; } }                             \
    float c0 = NEG_INF, c1 = NEG_INF, c2 = NEG_INF, c3 = NEG_INF;             \
    int   d0 = 0,       d1 = 8,       d2 = 16,      d3 = 24;                  \
    _Pragma("unroll")                                                         \
    for (int u = 0; u < 8; ++u) {                                             \
        float v0 = ((F) + tr[u])      + pv[u];                                \
        float v1 = ((F) + tr[u + 8])  + pv[u + 8];                            \
        float v2 = ((F) + tr[u + 16]) + pv[u + 16];                           \
        float v3 = ((F) + tr[u + 24]) + pv[u + 24];                           \
        d0 = (v0 > c0) ? u        : d0;  c0 = fmaxf(c0, v0);                  \
        d1 = (v1 > c1) ? (u + 8)  : d1;  c1 = fmaxf(c1, v1);                  \
        d2 = (v2 > c2) ? (u + 16) : d2;  c2 = fmaxf(c2, v2);                  \
        d3 = (v3 > c3) ? (u + 24) : d3;  c3 = fmaxf(c3, v3);                  \
    }                                                                         \
    if (c1 > c0) { c0 = c1; d0 = d1; }                                        \
    if (c3 > c2) { c2 = c3; d2 = d3; }                                        \
    if (c2 > c0) { c0 = c2; d0 = d2; }                                        \
    (OUTB) = c0; (OUTA) = i0 + d0;                                            \
} while (0)

__global__ __launch_bounds__(NTHR, 1)
void crf_viterbi_x2(const float* __restrict__ feats,
                    const float* __restrict__ trans,
                    const unsigned* __restrict__ candA,
                    const unsigned* __restrict__ candB,
                    float* __restrict__ out)
{
    extern __shared__ unsigned char bpbuf[];        // [NB][SS][TT]
    __shared__ __align__(16) float part[NB][2][TT]; // [batch][parity][tag]
    __shared__ float lastp[NB][TT];
    __shared__ int s_len[NB], s_ptr0[NB], s_clsA, s_clsB;

    const int tid  = threadIdx.x;
    const int warp = tid >> 5;
    const int lane = tid & 31;
    const int tag  = (warp << 4) | (lane & 15);
    const int seg  = lane >> 4;          // 0 or 1
    const int i0   = seg << 5;           // predecessor range [i0, i0+32)
    const int b0   = blockIdx.x * NB;    // first batch of this CTA

    // ---- transitions rows i0..i0+31 of column `tag` into registers
    float tr[32];
#pragma unroll
    for (int u = 0; u < 32; ++u) tr[u] = trans[(i0 + u) * TT + tag];

    // ---- identify mask buffer + encoding by content ----------------------
    // bit0: words in {0,1} -> i32; bit1: {0,0x3F800000} -> f32;
    // bit2: bytes in {0,1} -> u8;  bit3: halves in {0,0x3F80} -> bf16
    if (tid == 0) { s_len[0] = 0; s_len[1] = 0; s_clsA = 0xF; s_clsB = 0xF; }
    __syncthreads();
    {
        int fa = 0xF, fbc = 0xF;
        for (int s = tid; s < 512; s += NTHR) {
            unsigned w = candA[s];
            if (w > 1u) fa &= ~1;
            if (w != 0u && w != 0x3F800000u) fa &= ~2;
            if (w & 0xFEFEFEFEu) fa &= ~4;
            { unsigned hi = w >> 16, lo = w & 0xFFFFu;
              if (!((hi==0u||hi==0x3F80u) && (lo==0u||lo==0x3F80u))) fa &= ~8; }
            w = candB[s];
            if (w > 1u) fbc &= ~1;
            if (w != 0u && w != 0x3F800000u) fbc &= ~2;
            if (w & 0xFEFEFEFEu) fbc &= ~4;
            { unsigned hi = w >> 16, lo = w & 0xFFFFu;
              if (!((hi==0u||hi==0x3F80u) && (lo==0u||lo==0x3F80u))) fbc &= ~8; }
        }
        atomicAnd(&s_clsA, fa);
        atomicAnd(&s_clsB, fbc);
    }
    __syncthreads();
    const unsigned* maskw = s_clsA ? candA : candB;
    const int cls = s_clsA ? s_clsA : (s_clsB ? s_clsB : 1);

    // ---- sequence lengths for both batches --------------------------------
#pragma unroll
    for (int bi = 0; bi < NB; ++bi) {
        int lsum = 0;
        const int bb = b0 + bi;
        if (cls & 3) {
            const unsigned* m = maskw + bb * SS;
            for (int s = tid; s < SS; s += NTHR) lsum += (m[s] != 0u);
        } else if (cls & 4) {
            const unsigned char* m = (const unsigned char*)maskw + bb * SS;
            for (int s = tid; s < SS; s += NTHR) lsum += (m[s] != 0);
        } else {
            const unsigned short* m = (const unsigned short*)maskw + bb * SS;
            for (int s = tid; s < SS; s += NTHR) lsum += (m[s] != 0);
        }
        atomicAdd(&s_len[bi], lsum);
    }

    // ---- part0 per batch ----------------------------------------------------
    const float* fbA = feats + (b0 + 0) * SS * TT;
    const float* fbB = feats + (b0 + 1) * SS * TT;
    if (seg == 1) {                        // START row 62 = seg1, u = 30
        float pA = fbA[tag] + tr[30];
        part[0][0][tag] = pA;  lastp[0][tag] = pA;
        float pB = fbB[tag] + tr[30];
        part[1][0][tag] = pB;  lastp[1][tag] = pB;
    }
    __syncthreads();
    int lenA = s_len[0]; if (lenA < 1) lenA = 1; if (lenA > SS) lenA = SS;
    int lenB = s_len[1]; if (lenB < 1) lenB = 1; if (lenB > SS) lenB = SS;
    const int lpA = lenA - 1;
    const int lpB = lenB - 1;

    unsigned char* bpA = bpbuf;
    unsigned char* bpB = bpbuf + SS * TT;

    // ---- forward recurrence: both batches between one barrier pair ---------
    float fAn = fbA[TT + tag];
    float fBn = fbB[TT + tag];
    int buf = 0;
#pragma unroll 1
    for (int t = 1; t < SS; ++t) {
        const float fa = fAn;
        const float fbv = fBn;
        if (t + 1 < SS) {
            fAn = fbA[(t + 1) * TT + tag];
            fBn = fbB[(t + 1) * TT + tag];
        }

        float bA, bB2; int aA, aB2;
        REDUCE32(part[0][buf], fa,  bA,  aA);
        REDUCE32(part[1][buf], fbv, bB2, aB2);

        float oA = __shfl_xor_sync(0xffffffffu, bA, 16);
        int   oAa = __shfl_xor_sync(0xffffffffu, aA, 16);
        float oB = __shfl_xor_sync(0xffffffffu, bB2, 16);
        int   oBa = __shfl_xor_sync(0xffffffffu, aB2, 16);

        if (seg == 0) {
            float BA = bA;  int AA = aA;          // seg0 wins ties
            if (oA > BA) { BA = oA; AA = oAa; }
            part[0][buf ^ 1][tag] = BA;
            bpA[t * TT + tag] = (unsigned char)((t < lenA) ? AA : 0);
            if (t == lpA) lastp[0][tag] = BA;

            float BB = bB2; int AB = aB2;
            if (oB > BB) { BB = oB; AB = oBa; }
            part[1][buf ^ 1][tag] = BB;
            bpB[t * TT + tag] = (unsigned char)((t < lenB) ? AB : 0);
            if (t == lpB) lastp[1][tag] = BB;
        }
        buf ^= 1;
        __syncthreads();
    }

    // ---- pointer0 per batch: argmax_i( lastp[i] + trans[i][STOP_TAG] ) -----
#pragma unroll
    for (int bi = 0; bi < NB; ++bi) {
        float c0 = NEG_INF, c1 = NEG_INF, c2 = NEG_INF, c3 = NEG_INF;
        int   d0 = 0,       d1 = 8,       d2 = 16,      d3 = 24;
#pragma unroll
        for (int u = 0; u < 8; ++u) {
            float v0 = lastp[bi][i0 + u]      + tr[u];
            float v1 = lastp[bi][i0 + u + 8]  + tr[u + 8];
            float v2 = lastp[bi][i0 + u + 16] + tr[u + 16];
            float v3 = lastp[bi][i0 + u + 24] + tr[u + 24];
            d0 = (v0 > c0) ? u        : d0;  c0 = fmaxf(c0, v0);
            d1 = (v1 > c1) ? (u + 8)  : d1;  c1 = fmaxf(c1, v1);
            d2 = (v2 > c2) ? (u + 16) : d2;  c2 = fmaxf(c2, v2);
            d3 = (v3 > c3) ? (u + 24) : d3;  c3 = fmaxf(c3, v3);
        }
        if (c1 > c0) { c0 = c1; d0 = d1; }
        if (c3 > c2) { c2 = c3; d2 = d3; }
        if (c2 > c0) { c0 = c2; d0 = d2; }
        int ag = i0 + d0;

        float bo = __shfl_xor_sync(0xffffffffu, c0, 16);
        int   ao = __shfl_xor_sync(0xffffffffu, ag, 16);
        if (seg == 0 && tag == STOP_TAG) {
            int arg = ag;
            if (bo > c0) arg = ao;
            s_ptr0[bi] = arg;
        }
    }
    __syncthreads();

    // ---- backtrack: lanes 0/1 chase both batches concurrently ---------------
    if (tid < NB) {
        const int bi = tid;
        const int p0 = s_ptr0[bi];
        int lenX = s_len[bi]; if (lenX < 1) lenX = 1; if (lenX > SS) lenX = SS;
        const int lpX = lenX - 1;
        const unsigned char* bpX = bpbuf + bi * SS * TT;
        float* o = out + (b0 + bi) * SS;
        int ptr = p0;
        o[SS - 1] = (float)ptr;
        for (int k = SS - 2; k >= 0; --k) {
            ptr = (k == lpX) ? p0 : (int)bpX[(k + 1) * TT + ptr];
            o[k] = (float)ptr;
        }
    }
}

extern "C" void kernel_launch(void* const* d_in, const int* in_sizes, int n_in,
                              void* d_out, int out_size) {
    // feats = largest buffer, transitions = smallest; the two leftovers are
    // {mask, tags}, disambiguated by content inside the kernel.
    int fi = 0, ti = 0;
    for (int i = 1; i < n_in; ++i) {
        if (in_sizes[i] > in_sizes[fi]) fi = i;
        if (in_sizes[i] < in_sizes[ti]) ti = i;
    }
    int cA = -1, cB = -1;
    for (int i = 0; i < n_in; ++i) {
        if (i == fi || i == ti) continue;
        if (cA < 0) cA = i; else if (cB < 0) cB = i;
    }
    if (cA < 0) cA = ti;
    if (cB < 0) cB = cA;

    // 64 KB dynamic smem for back-pointers of 2 batches (non-stream call,
    // capture-safe, idempotent).
    cudaFuncSetAttribute(crf_viterbi_x2,
                         cudaFuncAttributeMaxDynamicSharedMemorySize, BP_BYTES);

    const int nbatch = out_size / SS;          // 128
    crf_viterbi_x2<<<nbatch / NB, NTHR, BP_BYTES>>>(
        (const float*)d_in[fi],
        (const float*)d_in[ti],
        (const unsigned*)d_in[cA],
        (const unsigned*)d_in[cB],
        (float*)d_out);
}

// round 10
// speedup vs baseline: 1.4592x; 1.4592x over previous
#include <cuda_runtime.h>

// CRF Viterbi decode: B=128, S=512, T=64.
// One CTA per batch, 256 threads = 8 warps (2 per SMSP for latency hiding).
// Warp w owns tags 8w..8w+7; lane = seg*8 + jloc, seg in 0..3 covers
// predecessors [16*seg, 16*seg+16). ONE __syncthreads per step; the 4
// segments combine inside the warp via shfl_xor(8) then shfl_xor(16) with
// an explicit min-index tie rule (bit-exact first-occurrence argmax).
// v = (f + trans[i][j]) + part[i] association preserved exactly.
// Output written as float32.

#define SS 512
#define TT 64
#define START_TAG 62
#define STOP_TAG 63
#define NEG_INF (-3.402823466e+38f)
#define NTHR 256

__global__ __launch_bounds__(NTHR, 1)
void crf_viterbi_w8(const float* __restrict__ feats,
                    const float* __restrict__ trans,
                    const unsigned* __restrict__ candA,
                    const unsigned* __restrict__ candB,
                    float* __restrict__ out)
{
    __shared__ __align__(16) float part[2][TT];
    __shared__ float lastp[TT];
    __shared__ unsigned char bp[SS][TT];   // bp[t][j], t>=1, mask-applied
    __shared__ int s_len, s_ptr0, s_clsA, s_clsB;

    const int tid  = threadIdx.x;
    const int b    = blockIdx.x;
    const int warp = tid >> 5;
    const int lane = tid & 31;
    const int tag  = (warp << 3) | (lane & 7);
    const int seg  = lane >> 3;          // 0..3
    const int i0   = seg << 4;           // predecessor range [i0, i0+16)

    float* o = out + b * SS;

    // ---- transitions rows i0..i0+15 of column `tag` into registers
    float tr[16];
#pragma unroll
    for (int u = 0; u < 16; ++u) tr[u] = trans[(i0 + u) * TT + tag];

    // ---- identify mask buffer + encoding by content ----------------------
    // bit0: words in {0,1} -> i32; bit1: {0,0x3F800000} -> f32;
    // bit2: bytes in {0,1} -> u8;  bit3: halves in {0,0x3F80} -> bf16
    if (tid == 0) { s_len = 0; s_clsA = 0xF; s_clsB = 0xF; }
    __syncthreads();
    {
        int fa = 0xF, fbc = 0xF;
        for (int s = tid; s < 512; s += NTHR) {
            unsigned w = candA[s];
            if (w > 1u) fa &= ~1;
            if (w != 0u && w != 0x3F800000u) fa &= ~2;
            if (w & 0xFEFEFEFEu) fa &= ~4;
            { unsigned hi = w >> 16, lo = w & 0xFFFFu;
              if (!((hi==0u||hi==0x3F80u) && (lo==0u||lo==0x3F80u))) fa &= ~8; }
            w = candB[s];
            if (w > 1u) fbc &= ~1;
            if (w != 0u && w != 0x3F800000u) fbc &= ~2;
            if (w & 0xFEFEFEFEu) fbc &= ~4;
            { unsigned hi = w >> 16, lo = w & 0xFFFFu;
              if (!((hi==0u||hi==0x3F80u) && (lo==0u||lo==0x3F80u))) fbc &= ~8; }
        }
        atomicAnd(&s_clsA, fa);
        atomicAnd(&s_clsB, fbc);
    }
    __syncthreads();
    const unsigned* maskw = s_clsA ? candA : candB;
    const int cls = s_clsA ? s_clsA : (s_clsB ? s_clsB : 1);

    // ---- sequence length = nonzero count in mask row b --------------------
    {
        int lsum = 0;
        if (cls & 3) {
            const unsigned* m = maskw + b * SS;
            for (int s = tid; s < SS; s += NTHR) lsum += (m[s] != 0u);
        } else if (cls & 4) {
            const unsigned char* m = (const unsigned char*)maskw + b * SS;
            for (int s = tid; s < SS; s += NTHR) lsum += (m[s] != 0);
        } else {
            const unsigned short* m = (const unsigned short*)maskw + b * SS;
            for (int s = tid; s < SS; s += NTHR) lsum += (m[s] != 0);
        }
        atomicAdd(&s_len, lsum);
    }

    // ---- part0 = feats[b,0,:] + transitions[START_TAG,:] ------------------
    const float* fb = feats + b * SS * TT;
    if (seg == 3) {                        // START row 62 = seg3, u = 14
        float p0v = fb[tag] + tr[14];
        part[0][tag] = p0v;
        lastp[tag]   = p0v;                // correct when last_pos == 0
    }
    __syncthreads();
    int len = s_len;
    if (len < 1)  len = 1;
    if (len > SS) len = SS;
    const int last_pos = len - 1;

    // ---- ftr for t = 1, prefetch feat for t = 2 ----------------------------
    float ftr[16];
    {
        float f1 = fb[TT + tag];
#pragma unroll
        for (int u = 0; u < 16; ++u) ftr[u] = f1 + tr[u];
    }
    float fnext = fb[2 * TT + tag];

    // ---- forward recurrence: ONE barrier per step ---------------------------
    int buf = 0;
#pragma unroll 1
    for (int t = 1; t < SS; ++t) {
        // read this segment's 16 partition values (vectorized broadcast)
        float pv[16];
        {
            const float4* p4 = (const float4*)(&part[buf][i0]);
#pragma unroll
            for (int q = 0; q < 4; ++q) {
                float4 v4 = p4[q];
                pv[4*q+0] = v4.x; pv[4*q+1] = v4.y;
                pv[4*q+2] = v4.z; pv[4*q+3] = v4.w;
            }
        }

        // 2 chains of 8 contiguous preds; fmax value chain, pred-select index
        float c0 = NEG_INF, c1 = NEG_INF;
        int   d0 = 0,       d1 = 8;
#pragma unroll
        for (int u = 0; u < 8; ++u) {
            float v0 = ftr[u]     + pv[u];
            float v1 = ftr[u + 8] + pv[u + 8];
            d0 = (v0 > c0) ? u       : d0;  c0 = fmaxf(c0, v0);
            d1 = (v1 > c1) ? (u + 8) : d1;  c1 = fmaxf(c1, v1);
        }
        if (c1 > c0) { c0 = c1; d0 = d1; }   // ascending, strict >
        float bg = c0;
        int   ag = i0 + d0;

        // cross-segment combine inside the warp; explicit min-index tie rule
        {
            float bo = __shfl_xor_sync(0xffffffffu, bg, 8);
            int   ao = __shfl_xor_sync(0xffffffffu, ag, 8);
            bool take = (bo > bg) || (bo == bg && ao < ag);
            bg = take ? bo : bg;  ag = take ? ao : ag;
            bo = __shfl_xor_sync(0xffffffffu, bg, 16);
            ao = __shfl_xor_sync(0xffffffffu, ag, 16);
            take = (bo > bg) || (bo == bg && ao < ag);
            bg = take ? bo : bg;  ag = take ? ao : ag;
        }

        if (seg == 0) {                      // one writer per tag
            part[buf ^ 1][tag] = bg;
            bp[t][tag] = (unsigned char)((t < len) ? ag : 0);
            if (t == last_pos) lastp[tag] = bg;
        }

        // build ftr for step t+1 BEFORE the barrier (overlaps arrive skew)
        {
            float f = fnext;
            if (t + 2 < SS) fnext = fb[(t + 2) * TT + tag];
#pragma unroll
            for (int u = 0; u < 16; ++u) ftr[u] = f + tr[u];
        }

        buf ^= 1;
        __syncthreads();
    }

    // ---- pointer0 = argmax_i( lastp[i] + trans[i][STOP_TAG] ) --------------
    {
        float c0 = NEG_INF, c1 = NEG_INF;
        int   d0 = 0,       d1 = 8;
#pragma unroll
        for (int u = 0; u < 8; ++u) {
            float v0 = lastp[i0 + u]     + tr[u];
            float v1 = lastp[i0 + u + 8] + tr[u + 8];
            d0 = (v0 > c0) ? u       : d0;  c0 = fmaxf(c0, v0);
            d1 = (v1 > c1) ? (u + 8) : d1;  c1 = fmaxf(c1, v1);
        }
        if (c1 > c0) { c0 = c1; d0 = d1; }
        float bg = c0;
        int   ag = i0 + d0;

        float bo = __shfl_xor_sync(0xffffffffu, bg, 8);
        int   ao = __shfl_xor_sync(0xffffffffu, ag, 8);
        bool take = (bo > bg) || (bo == bg && ao < ag);
        bg = take ? bo : bg;  ag = take ? ao : ag;
        bo = __shfl_xor_sync(0xffffffffu, bg, 16);
        ao = __shfl_xor_sync(0xffffffffu, ag, 16);
        take = (bo > bg) || (bo == bg && ao < ag);
        ag = take ? ao : ag;

        if (seg == 0 && tag == STOP_TAG) s_ptr0 = ag;
        __syncthreads();
    }

    // ---- backtrack, float output ---------------------------------------------
    if (tid == 0) {
        const int p0 = s_ptr0;
        int ptr = p0;
        o[SS - 1] = (float)ptr;
        for (int k = SS - 2; k >= 0; --k) {
            ptr = (k == last_pos) ? p0 : (int)bp[k + 1][ptr];
            o[k] = (float)ptr;
        }
    }
}

extern "C" void kernel_launch(void* const* d_in, const int* in_sizes, int n_in,
                              void* d_out, int out_size) {
    // feats = largest buffer, transitions = smallest; the two leftovers are
    // {mask, tags}, disambiguated by content inside the kernel.
    int fi = 0, ti = 0;
    for (int i = 1; i < n_in; ++i) {
        if (in_sizes[i] > in_sizes[fi]) fi = i;
        if (in_sizes[i] < in_sizes[ti]) ti = i;
    }
    int cA = -1, cB = -1;
    for (int i = 0; i < n_in; ++i) {
        if (i == fi || i == ti) continue;
        if (cA < 0) cA = i; else if (cB < 0) cB = i;
    }
    if (cA < 0) cA = ti;
    if (cB < 0) cB = cA;

    const int nbatch = out_size / SS;          // 128
    crf_viterbi_w8<<<nbatch, NTHR>>>((const float*)d_in[fi],
                                     (const float*)d_in[ti],
                                     (const unsigned*)d_in[cA],
                                     (const unsigned*)d_in[cB],
                                     (float*)d_out);
}

// round 12
// speedup vs baseline: 1.6724x; 1.1462x over previous
#include <cuda_runtime.h>

// CRF Viterbi decode: B=128, S=512, T=64.
// One CTA per batch, 128 threads. Warp w owns tags 16w..16w+15;
// lanes 0-15 = predecessor seg [0,32), lanes 16-31 = seg [32,64).
// ONE __syncthreads per step; cross-segment combine via __shfl_xor(16).
// Issue-count optimized: packed add.rn.f32x2 for both add families,
// chains seeded with candidate 0, bp stored unmasked (masking done in
// backtrack). Bit-exact with reference: v = (f + trans[i][j]) + part[i];
// first-occurrence argmax (fmax value chains, pred-select indices,
// ascending strict-> combines, seg0 wins ties). Output float32.

#define SS 512
#define TT 64
#define START_TAG 62
#define STOP_TAG 63
#define NEG_INF (-3.402823466e+38f)
#define NTHR 128

typedef unsigned long long ull;

__device__ __forceinline__ ull addx2(ull a, ull b) {
    ull r;
    asm("add.rn.f32x2 %0, %1, %2;" : "=l"(r) : "l"(a), "l"(b));
    return r;
}
__device__ __forceinline__ ull packx2(float lo, float hi) {
    ull r;
    asm("mov.b64 %0, {%1, %2};" : "=l"(r) : "f"(lo), "f"(hi));
    return r;
}
__device__ __forceinline__ void unpackx2(ull v, float& lo, float& hi) {
    asm("mov.b64 {%0, %1}, %2;" : "=f"(lo), "=f"(hi) : "l"(v));
}

// argmax chain over 4 packed pairs (8 candidates), seeded with element 0.
// Indices BASE..BASE+7; strict > keeps earliest on ties.
#define CHAIN8(CVAL, CIDX, VV, BASE) do {                                    \
    float lo_, hi_;                                                          \
    unpackx2((VV)[0], lo_, hi_);                                             \
    CVAL = lo_; CIDX = (BASE);                                               \
    CIDX = (hi_ > CVAL) ? (BASE) + 1 : CIDX;  CVAL = fmaxf(CVAL, hi_);       \
    _Pragma("unroll")                                                        \
    for (int q_ = 1; q_ < 4; ++q_) {                                         \
        unpackx2((VV)[q_], lo_, hi_);                                        \
        CIDX = (lo_ > CVAL) ? (BASE) + 2*q_     : CIDX;                      \
        CVAL = fmaxf(CVAL, lo_);                                             \
        CIDX = (hi_ > CVAL) ? (BASE) + 2*q_ + 1 : CIDX;                      \
        CVAL = fmaxf(CVAL, hi_);                                             \
    }                                                                        \
} while (0)

__global__ __launch_bounds__(NTHR, 1)
void crf_viterbi_px(const float* __restrict__ feats,
                    const float* __restrict__ trans,
                    const unsigned* __restrict__ candA,
                    const unsigned* __restrict__ candB,
                    float* __restrict__ out)
{
    __shared__ __align__(16) float part[2][TT];
    __shared__ float lastp[TT];
    __shared__ unsigned char bp[SS][TT];   // bp[t][j], t>=1, UNMASKED
    __shared__ int s_len, s_ptr0, s_clsA, s_clsB;

    const int tid  = threadIdx.x;
    const int b    = blockIdx.x;
    const int warp = tid >> 5;
    const int lane = tid & 31;
    const int tag  = (warp << 4) | (lane & 15);
    const int seg  = lane >> 4;          // 0 or 1
    const int i0   = seg << 5;           // predecessor range [i0, i0+32)

    float* o = out + b * SS;

    // ---- transitions rows i0..i0+31 of column `tag`, packed in pairs
    ull trp[16];
#pragma unroll
    for (int u = 0; u < 16; ++u)
        trp[u] = packx2(trans[(i0 + 2*u) * TT + tag],
                        trans[(i0 + 2*u + 1) * TT + tag]);

    // ---- identify mask buffer + encoding by content ----------------------
    // bit0: words in {0,1} -> i32; bit1: {0,0x3F800000} -> f32;
    // bit2: bytes in {0,1} -> u8;  bit3: halves in {0,0x3F80} -> bf16
    if (tid == 0) { s_len = 0; s_clsA = 0xF; s_clsB = 0xF; }
    __syncthreads();
    {
        int fa = 0xF, fbc = 0xF;
        for (int s = tid; s < 512; s += NTHR) {
            unsigned w = candA[s];
            if (w > 1u) fa &= ~1;
            if (w != 0u && w != 0x3F800000u) fa &= ~2;
            if (w & 0xFEFEFEFEu) fa &= ~4;
            { unsigned hi = w >> 16, lo = w & 0xFFFFu;
              if (!((hi==0u||hi==0x3F80u) && (lo==0u||lo==0x3F80u))) fa &= ~8; }
            w = candB[s];
            if (w > 1u) fbc &= ~1;
            if (w != 0u && w != 0x3F800000u) fbc &= ~2;
            if (w & 0xFEFEFEFEu) fbc &= ~4;
            { unsigned hi = w >> 16, lo = w & 0xFFFFu;
              if (!((hi==0u||hi==0x3F80u) && (lo==0u||lo==0x3F80u))) fbc &= ~8; }
        }
        atomicAnd(&s_clsA, fa);
        atomicAnd(&s_clsB, fbc);
    }
    __syncthreads();
    const unsigned* maskw = s_clsA ? candA : candB;
    const int cls = s_clsA ? s_clsA : (s_clsB ? s_clsB : 1);

    // ---- sequence length = nonzero count in mask row b --------------------
    {
        int lsum = 0;
        if (cls & 3) {
            const unsigned* m = maskw + b * SS;
            for (int s = tid; s < SS; s += NTHR) lsum += (m[s] != 0u);
        } else if (cls & 4) {
            const unsigned char* m = (const unsigned char*)maskw + b * SS;
            for (int s = tid; s < SS; s += NTHR) lsum += (m[s] != 0);
        } else {
            const unsigned short* m = (const unsigned short*)maskw + b * SS;
            for (int s = tid; s < SS; s += NTHR) lsum += (m[s] != 0);
        }
        atomicAdd(&s_len, lsum);
    }

    // ---- part0 = feats[b,0,:] + transitions[START_TAG,:] ------------------
    const float* fb = feats + b * SS * TT;
    if (seg == 1) {                        // START row 62 = seg1, pair 15 lo
        float t62, t63;
        unpackx2(trp[15], t62, t63);
        float p0v = fb[tag] + t62;
        part[0][tag] = p0v;
        lastp[tag]   = p0v;                // correct when last_pos == 0
    }
    __syncthreads();
    int len = s_len;
    if (len < 1)  len = 1;
    if (len > SS) len = SS;
    const int last_pos = len - 1;

    // ---- ftr (packed) for t = 1, prefetch feat for t = 2 -------------------
    ull ftr[16];
    {
        float f1 = fb[TT + tag];
        ull fp = packx2(f1, f1);
#pragma unroll
        for (int u = 0; u < 16; ++u) ftr[u] = addx2(fp, trp[u]);
    }
    float fnext = fb[2 * TT + tag];

    // ---- forward recurrence: ONE barrier per step ---------------------------
    int buf = 0;
#pragma unroll 1
    for (int t = 1; t < SS; ++t) {
        // packed partition pairs for this segment (LDS.128)
        ull pvp[16];
        {
            const longlong2* p2 = (const longlong2*)(&part[buf][i0]);
#pragma unroll
            for (int q = 0; q < 8; ++q) {
                longlong2 w = p2[q];
                pvp[2*q]   = (ull)w.x;
                pvp[2*q+1] = (ull)w.y;
            }
        }

        // packed candidate values: v = ftr + pv (exact (f+tr)+p association)
        ull vv[16];
#pragma unroll
        for (int q = 0; q < 16; ++q) vv[q] = addx2(ftr[q], pvp[q]);

        float c0, c1, c2, c3; int d0, d1, d2, d3;
        CHAIN8(c0, d0, vv + 0,  0);
        CHAIN8(c1, d1, vv + 4,  8);
        CHAIN8(c2, d2, vv + 8,  16);
        CHAIN8(c3, d3, vv + 12, 24);

        // ascending combine; strict > keeps the earliest index on ties
        if (c1 > c0) { c0 = c1; d0 = d1; }
        if (c3 > c2) { c2 = c3; d2 = d3; }
        if (c2 > c0) { c0 = c2; d0 = d2; }
        float bg = c0;
        int   ag = i0 + d0;

        // cross-segment combine inside the warp (lanes l <-> l^16)
        float bo = __shfl_xor_sync(0xffffffffu, bg, 16);
        int   ao = __shfl_xor_sync(0xffffffffu, ag, 16);

        if (seg == 0) {
            float best = bg;  int arg = ag;      // seg0 wins ties
            if (bo > best) { best = bo; arg = ao; }
            part[buf ^ 1][tag] = best;
            bp[t][tag] = (unsigned char)arg;     // unmasked; masked in backtrack
            if (t == last_pos) lastp[tag] = best;
        }

        // build packed ftr for step t+1 BEFORE the barrier
        {
            float f = fnext;
            if (t + 2 < SS) fnext = fb[(t + 2) * TT + tag];
            ull fp = packx2(f, f);
#pragma unroll
            for (int u = 0; u < 16; ++u) ftr[u] = addx2(fp, trp[u]);
        }

        buf ^= 1;
        __syncthreads();
    }

    // ---- pointer0 = argmax_i( lastp[i] + trans[i][STOP_TAG] ) --------------
    {
        ull vv[16];
        const longlong2* p2 = (const longlong2*)(&lastp[i0]);
#pragma unroll
        for (int q = 0; q < 8; ++q) {
            longlong2 w = p2[q];
            vv[2*q]   = addx2(trp[2*q],   (ull)w.x);
            vv[2*q+1] = addx2(trp[2*q+1], (ull)w.y);
        }
        float c0, c1, c2, c3; int d0, d1, d2, d3;
        CHAIN8(c0, d0, vv + 0,  0);
        CHAIN8(c1, d1, vv + 4,  8);
        CHAIN8(c2, d2, vv + 8,  16);
        CHAIN8(c3, d3, vv + 12, 24);
        if (c1 > c0) { c0 = c1; d0 = d1; }
        if (c3 > c2) { c2 = c3; d2 = d3; }
        if (c2 > c0) { c0 = c2; d0 = d2; }
        float bg = c0;
        int   ag = i0 + d0;

        // only threads with tag == STOP_TAG hold trans[i][STOP_TAG]; the shfl
        // pairs lanes 15/31 of warp 3, both of which have tag 63.
        float bo = __shfl_xor_sync(0xffffffffu, bg, 16);
        int   ao = __shfl_xor_sync(0xffffffffu, ag, 16);
        if (seg == 0 && tag == STOP_TAG) {
            int arg = ag;
            if (bo > bg) arg = ao;
            s_ptr0 = arg;
        }
        __syncthreads();
    }

    // ---- backtrack, float output; masking applied here -----------------------
    // Reference: decode[last] slot (seq index SS-1) holds pointer0; for
    // k > last_pos the masked bp rows were 0 -> pointer becomes 0; at
    // k == last_pos the pointer resets to p0; below that, normal chase.
    if (tid == 0) {
        const int p0 = s_ptr0;
        o[SS - 1] = (float)p0;
        int ptr = p0;
        for (int k = SS - 2; k >= 0; --k) {
            if (k > last_pos)       ptr = 0;
            else if (k == last_pos) ptr = p0;
            else                    ptr = (int)bp[k + 1][ptr];
            o[k] = (float)ptr;
        }
    }
}

extern "C" void kernel_launch(void* const* d_in, const int* in_sizes, int n_in,
                              void* d_out, int out_size) {
    // feats = largest buffer, transitions = smallest; the two leftovers are
    // {mask, tags}, disambiguated by content inside the kernel.
    int fi = 0, ti = 0;
    for (int i = 1; i < n_in; ++i) {
        if (in_sizes[i] > in_sizes[fi]) fi = i;
        if (in_sizes[i] < in_sizes[ti]) ti = i;
    }
    int cA = -1, cB = -1;
    for (int i = 0; i < n_in; ++i) {
        if (i == fi || i == ti) continue;
        if (cA < 0) cA = i; else if (cB < 0) cB = i;
    }
    if (cA < 0) cA = ti;
    if (cB < 0) cB = cA;

    const int nbatch = out_size / SS;          // 128
    crf_viterbi_px<<<nbatch, NTHR>>>((const float*)d_in[fi],
                                     (const float*)d_in[ti],
                                     (const unsigned*)d_in[cA],
                                     (const unsigned*)d_in[cB],
                                     (float*)d_out);
}